// round 3
// baseline (speedup 1.0000x reference)
#include <cuda_runtime.h>
#include <cuda_bf16.h>
#include <math.h>

#define N_NODES   100000
#define N_EDGES   1600000
#define E_TOT     (N_EDGES + N_NODES)
#define IN_CH     128
#define HID       64
#define OUT_CH    16
#define N_GRAPHS  512
#define NEG_SLOPE 0.2f

// ---------------- scratch (device globals; no allocation allowed) ----------------
__device__ float g_xl[(size_t)N_NODES * HID];
__device__ float g_xr[(size_t)N_NODES * HID];
__device__ float g_agg[(size_t)N_NODES * HID];
__device__ float g_z[N_NODES];
__device__ float g_h[(size_t)N_NODES * HID];
__device__ float g_pool[N_GRAPHS * HID];
__device__ float g_cnt[N_GRAPHS];
__device__ float g_y[N_GRAPHS * HID];
__device__ float g_mu[HID];
__device__ float g_rsig[HID];
__device__ int   g_is64;   // 1 if edge_index/batch delivered as int64, 0 if int32

// ---------------- dtype detection ----------------
// If data is int64 with values in [0, 1e5), every odd 32-bit word is 0.
// For genuine int32 random indices the chance all 32 odd words are 0 is ~0.
__global__ void detect_kernel(const int* __restrict__ w) {
    int ok64 = 1;
    for (int i = 0; i < 32; i++)
        if (w[2 * i + 1] != 0) ok64 = 0;
    g_is64 = ok64;
}

__device__ __forceinline__ int load_idx(const void* p, long long i) {
    if (g_is64) return (int)((const long long*)p)[i];
    return ((const int*)p)[i];
}

// ---------------- utility: zero fill ----------------
__global__ void zero_kernel(float* __restrict__ p, int n) {
    int i = blockIdx.x * blockDim.x + threadIdx.x;
    if (i < n) p[i] = 0.0f;
}

// ---------------- dual linear: XL = X@Wl + bl, XR = X@Wr + br ----------------
template <int IN>
__global__ void dual_linear_kernel(const float* __restrict__ X,
                                   const float* __restrict__ Wl, const float* __restrict__ bl,
                                   const float* __restrict__ Wr, const float* __restrict__ br,
                                   float* __restrict__ XL, float* __restrict__ XR) {
    int node0 = blockIdx.x * 4;
    int sub   = threadIdx.x >> 6;    // 0..3
    int c     = threadIdx.x & 63;    // 0..63
    __shared__ float xs[4][IN];

    for (int i = threadIdx.x; i < 4 * IN; i += 256) {
        int nn = i / IN, kk = i % IN;
        xs[nn][kk] = X[(size_t)(node0 + nn) * IN + kk];
    }
    __syncthreads();

    float al = bl[c];
    float ar = br[c];
    const float* xp = xs[sub];
#pragma unroll 8
    for (int k = 0; k < IN; k++) {
        float xv = xp[k];
        al = fmaf(xv, Wl[k * HID + c], al);
        ar = fmaf(xv, Wr[k * HID + c], ar);
    }
    size_t n = (size_t)(node0 + sub);
    XL[n * HID + c] = al;
    XR[n * HID + c] = ar;
}

// ---------------- edge pass: one warp per edge ----------------
// e = att . LeakyReLU(xl[src] + xr[dst]); a = exp(e)  (softmax max-subtraction
// is a mathematical no-op for the normalized result; |e| is O(1) here).
// Accumulate z[dst] += a, agg[dst][:] += a * xl[src][:].
__global__ void edge_kernel(const void* __restrict__ ei,
                            const float* __restrict__ att,
                            const float* __restrict__ XL,
                            const float* __restrict__ XR,
                            float* __restrict__ AGG,
                            float* __restrict__ Z) {
    int eid = blockIdx.x * (blockDim.x >> 5) + (threadIdx.x >> 5);
    if (eid >= E_TOT) return;
    int lane = threadIdx.x & 31;

    int src, dst;
    if (eid < N_EDGES) {
        src = load_idx(ei, eid);
        dst = load_idx(ei, (long long)N_EDGES + eid);
    } else {
        src = dst = eid - N_EDGES;   // self loops appended
    }

    float2 l = ((const float2*)(XL + (size_t)src * HID))[lane];
    float2 r = ((const float2*)(XR + (size_t)dst * HID))[lane];
    float2 a2 = ((const float2*)att)[lane];

    float hx = l.x + r.x;
    float hy = l.y + r.y;
    hx = (hx >= 0.0f) ? hx : NEG_SLOPE * hx;
    hy = (hy >= 0.0f) ? hy : NEG_SLOPE * hy;

    float e = a2.x * hx + a2.y * hy;
#pragma unroll
    for (int o = 16; o; o >>= 1) e += __shfl_xor_sync(0xffffffffu, e, o);

    float a = __expf(e);

    if (lane == 0) atomicAdd(&Z[dst], a);
    float* aggp = AGG + (size_t)dst * HID + 2 * lane;
    atomicAdd(aggp,     a * l.x);
    atomicAdd(aggp + 1, a * l.y);
}

// ---------------- node finalize: h = act(agg / z + bias) ----------------
__global__ void finalize_kernel(const float* __restrict__ AGG, const float* __restrict__ Z,
                                const float* __restrict__ bias, float* __restrict__ OUT,
                                int do_relu) {
    int i = blockIdx.x * blockDim.x + threadIdx.x;
    if (i >= N_NODES * HID) return;
    int n = i >> 6;
    int c = i & 63;
    float v = AGG[i] / Z[n] + bias[c];
    if (do_relu) v = fmaxf(v, 0.0f);
    OUT[i] = v;
}

// ---------------- global mean pool (sums + counts) ----------------
__global__ void pool_kernel(const void* __restrict__ batch,
                            const float* __restrict__ H,
                            float* __restrict__ POOL, float* __restrict__ CNT) {
    int n = blockIdx.x * (blockDim.x >> 5) + (threadIdx.x >> 5);
    if (n >= N_NODES) return;
    int lane = threadIdx.x & 31;
    int g = load_idx(batch, n);
    float2 v = ((const float2*)(H + (size_t)n * HID))[lane];
    atomicAdd(&POOL[g * HID + 2 * lane],     v.x);
    atomicAdd(&POOL[g * HID + 2 * lane + 1], v.y);
    if (lane == 0) atomicAdd(&CNT[g], 1.0f);
}

// ---------------- head: fc1 ----------------
__global__ void fc1_kernel(const float* __restrict__ POOL, const float* __restrict__ CNT,
                           const float* __restrict__ W, const float* __restrict__ b,
                           float* __restrict__ Y) {
    int gi = blockIdx.x;          // 512
    int c  = threadIdx.x;         // 64
    __shared__ float gs[HID];
    float cnt = fmaxf(CNT[gi], 1.0f);
    gs[c] = POOL[gi * HID + c] / cnt;
    __syncthreads();
    float acc = b[c];
#pragma unroll 8
    for (int k = 0; k < HID; k++) acc = fmaf(gs[k], W[k * HID + c], acc);
    Y[gi * HID + c] = acc;
}

// ---------------- head: batchnorm stats (training-mode batch stats) ----------------
__global__ void bn_stats_kernel(const float* __restrict__ Y,
                                float* __restrict__ MU, float* __restrict__ RSIG) {
    int c = threadIdx.x;          // 64
    float s = 0.0f, s2 = 0.0f;
    for (int g = 0; g < N_GRAPHS; g++) {
        float v = Y[g * HID + c];
        s += v;
        s2 += v * v;
    }
    float mu  = s * (1.0f / N_GRAPHS);
    float var = s2 * (1.0f / N_GRAPHS) - mu * mu;
    MU[c]   = mu;
    RSIG[c] = rsqrtf(var + 1e-5f);
}

// ---------------- head: bn -> relu -> fc2 -> log_softmax ----------------
__global__ void head_kernel(const float* __restrict__ Y,
                            const float* __restrict__ MU, const float* __restrict__ RSIG,
                            const float* __restrict__ gamma, const float* __restrict__ beta,
                            const float* __restrict__ W2, const float* __restrict__ b2,
                            float* __restrict__ OUT) {
    int gi = blockIdx.x;          // 512
    int t  = threadIdx.x;         // 64
    __shared__ float ys[HID];
    __shared__ float os[OUT_CH];
    float v = Y[gi * HID + t];
    v = gamma[t] * (v - MU[t]) * RSIG[t] + beta[t];
    ys[t] = fmaxf(v, 0.0f);
    __syncthreads();
    if (t < OUT_CH) {
        float acc = b2[t];
#pragma unroll 8
        for (int k = 0; k < HID; k++) acc = fmaf(ys[k], W2[k * OUT_CH + t], acc);
        os[t] = acc;
    }
    __syncthreads();
    if (t == 0) {
        float m = -1e30f;
#pragma unroll
        for (int j = 0; j < OUT_CH; j++) m = fmaxf(m, os[j]);
        float s = 0.0f;
#pragma unroll
        for (int j = 0; j < OUT_CH; j++) s += expf(os[j] - m);
        float lse = m + logf(s);
        for (int j = 0; j < OUT_CH; j++) OUT[gi * OUT_CH + j] = os[j] - lse;
    }
}

// ---------------- launch ----------------
extern "C" void kernel_launch(void* const* d_in, const int* in_sizes, int n_in,
                              void* d_out, int out_size) {
    const float* x      = (const float*)d_in[0];
    const void*  ei     = d_in[1];
    const void*  batch  = d_in[2];
    const float* W_l1   = (const float*)d_in[3];
    const float* b_l1   = (const float*)d_in[4];
    const float* W_r1   = (const float*)d_in[5];
    const float* b_r1   = (const float*)d_in[6];
    const float* att1   = (const float*)d_in[7];
    const float* bias1  = (const float*)d_in[8];
    const float* W_l2   = (const float*)d_in[9];
    const float* b_l2   = (const float*)d_in[10];
    const float* W_r2   = (const float*)d_in[11];
    const float* b_r2   = (const float*)d_in[12];
    const float* att2   = (const float*)d_in[13];
    const float* bias2  = (const float*)d_in[14];
    const float* W_fc1  = (const float*)d_in[15];
    const float* b_fc1  = (const float*)d_in[16];
    const float* gamma  = (const float*)d_in[17];
    const float* beta   = (const float*)d_in[18];
    const float* W_fc2  = (const float*)d_in[19];
    const float* b_fc2  = (const float*)d_in[20];
    float*       out    = (float*)d_out;

    // Resolve scratch symbol addresses (query only; no allocation).
    float *xl, *xr, *agg, *z, *h, *pool, *cnt, *y, *mu, *rsig;
    cudaGetSymbolAddress((void**)&xl,   g_xl);
    cudaGetSymbolAddress((void**)&xr,   g_xr);
    cudaGetSymbolAddress((void**)&agg,  g_agg);
    cudaGetSymbolAddress((void**)&z,    g_z);
    cudaGetSymbolAddress((void**)&h,    g_h);
    cudaGetSymbolAddress((void**)&pool, g_pool);
    cudaGetSymbolAddress((void**)&cnt,  g_cnt);
    cudaGetSymbolAddress((void**)&y,    g_y);
    cudaGetSymbolAddress((void**)&mu,   g_mu);
    cudaGetSymbolAddress((void**)&rsig, g_rsig);

    const int NH = N_NODES * HID;
    dim3 b256(256);

    // ---- detect int32 vs int64 index layout ----
    detect_kernel<<<1, 1>>>((const int*)ei);

    // ---- layer 1 ----
    zero_kernel<<<(NH + 255) / 256, b256>>>(agg, NH);
    zero_kernel<<<(N_NODES + 255) / 256, b256>>>(z, N_NODES);
    dual_linear_kernel<IN_CH><<<N_NODES / 4, b256>>>(x, W_l1, b_l1, W_r1, b_r1, xl, xr);
    edge_kernel<<<(E_TOT + 7) / 8, b256>>>(ei, att1, xl, xr, agg, z);
    finalize_kernel<<<(NH + 255) / 256, b256>>>(agg, z, bias1, h, 1);

    // ---- layer 2 ----
    zero_kernel<<<(NH + 255) / 256, b256>>>(agg, NH);
    zero_kernel<<<(N_NODES + 255) / 256, b256>>>(z, N_NODES);
    dual_linear_kernel<HID><<<N_NODES / 4, b256>>>(h, W_l2, b_l2, W_r2, b_r2, xl, xr);
    edge_kernel<<<(E_TOT + 7) / 8, b256>>>(ei, att2, xl, xr, agg, z);
    finalize_kernel<<<(NH + 255) / 256, b256>>>(agg, z, bias2, h, 0);

    // ---- pool + head ----
    zero_kernel<<<(N_GRAPHS * HID + 255) / 256, b256>>>(pool, N_GRAPHS * HID);
    zero_kernel<<<(N_GRAPHS + 255) / 256, b256>>>(cnt, N_GRAPHS);
    pool_kernel<<<(N_NODES + 7) / 8, b256>>>(batch, h, pool, cnt);
    fc1_kernel<<<N_GRAPHS, HID>>>(pool, cnt, W_fc1, b_fc1, y);
    bn_stats_kernel<<<1, HID>>>(y, mu, rsig);
    head_kernel<<<N_GRAPHS, HID>>>(y, mu, rsig, gamma, beta, W_fc2, b_fc2, out);
}

// round 4
// speedup vs baseline: 1.6847x; 1.6847x over previous
#include <cuda_runtime.h>
#include <cuda_bf16.h>
#include <math.h>

#define N_NODES   100000
#define N_EDGES   1600000
#define E_TOT     (N_EDGES + N_NODES)
#define IN_CH     128
#define HID       64
#define OUT_CH    16
#define N_GRAPHS  512
#define NEG_SLOPE 0.2f

// ---------------- scratch (device globals; no allocation allowed) ----------------
__device__ float g_xl[(size_t)N_NODES * HID];
__device__ float g_xr[(size_t)N_NODES * HID];
__device__ float g_agg[(size_t)N_NODES * HID];
__device__ float g_z[N_NODES];
__device__ float g_h[(size_t)N_NODES * HID];
__device__ float g_pool[N_GRAPHS * HID];
__device__ float g_cnt[N_GRAPHS];
__device__ float g_y[N_GRAPHS * HID];
__device__ float g_mu[HID];
__device__ float g_rsig[HID];
__device__ int   g_is64;   // 1 if edge_index/batch delivered as int64, 0 if int32

// ---------------- dtype detection ----------------
__global__ void detect_kernel(const int* __restrict__ w) {
    int ok64 = 1;
    for (int i = 0; i < 32; i++)
        if (w[2 * i + 1] != 0) ok64 = 0;
    g_is64 = ok64;
}

__device__ __forceinline__ int load_idx(const void* p, long long i) {
    if (g_is64) return (int)((const long long*)p)[i];
    return ((const int*)p)[i];
}

// ---------------- utility: zero fill ----------------
__global__ void zero_kernel(float* __restrict__ p, int n) {
    int i = blockIdx.x * blockDim.x + threadIdx.x;
    if (i < n) p[i] = 0.0f;
}

// ---------------- dual linear v2: 32 nodes/block, 8 nodes/thread ----------------
// thread (sub,c): channels c for nodes node0+sub*8 .. +7.  Each W element load
// feeds 8 FMAs per matrix; x staged in shared, read as float4.
template <int IN>
__global__ __launch_bounds__(256) void dual_linear_kernel(
        const float* __restrict__ X,
        const float* __restrict__ Wl, const float* __restrict__ bl,
        const float* __restrict__ Wr, const float* __restrict__ br,
        float* __restrict__ XL, float* __restrict__ XR) {
    int node0 = blockIdx.x * 32;
    int c     = threadIdx.x & 63;    // 0..63
    int sub   = threadIdx.x >> 6;    // 0..3
    __shared__ float xs[32][IN];

    // cooperative load: 32 rows of IN floats, float4-coalesced
    for (int i = threadIdx.x; i < 32 * (IN / 4); i += 256) {
        int row = i / (IN / 4), col = i % (IN / 4);
        ((float4*)xs[row])[col] =
            ((const float4*)(X + (size_t)(node0 + row) * IN))[col];
    }
    __syncthreads();

    float accl[8], accr[8];
    float bv_l = bl[c], bv_r = br[c];
#pragma unroll
    for (int n = 0; n < 8; n++) { accl[n] = bv_l; accr[n] = bv_r; }

    const float (*xp)[IN] = (const float (*)[IN])xs[sub * 8];

    for (int k0 = 0; k0 < IN; k0 += 4) {
        float4 xv[8];
#pragma unroll
        for (int n = 0; n < 8; n++)
            xv[n] = *(const float4*)&xp[n][k0];
#pragma unroll
        for (int kk = 0; kk < 4; kk++) {
            float wl = Wl[(k0 + kk) * HID + c];
            float wr = Wr[(k0 + kk) * HID + c];
#pragma unroll
            for (int n = 0; n < 8; n++) {
                float xvv = (kk == 0) ? xv[n].x : (kk == 1) ? xv[n].y
                          : (kk == 2) ? xv[n].z : xv[n].w;
                accl[n] = fmaf(xvv, wl, accl[n]);
                accr[n] = fmaf(xvv, wr, accr[n]);
            }
        }
    }

#pragma unroll
    for (int n = 0; n < 8; n++) {
        size_t node = (size_t)(node0 + sub * 8 + n);
        XL[node * HID + c] = accl[n];
        XR[node * HID + c] = accr[n];
    }
}

// ---------------- edge pass v2: 16 lanes/edge, float4 + red.v4 ----------------
// e = att . LeakyReLU(xl[src] + xr[dst]); a = exp(e)  (softmax max-subtraction
// cancels in the normalized result; |e| is O(1) here).
__global__ void edge_kernel(const void* __restrict__ ei,
                            const float* __restrict__ att,
                            const float* __restrict__ XL,
                            const float* __restrict__ XR,
                            float* __restrict__ AGG,
                            float* __restrict__ Z) {
    int lane = threadIdx.x & 31;
    int half = lane >> 4;            // 0/1: which edge of the pair
    int hl   = lane & 15;            // lane within half-warp
    int eid  = (blockIdx.x * (blockDim.x >> 5) + (threadIdx.x >> 5)) * 2 + half;
    if (eid >= E_TOT) return;

    int src, dst;
    if (eid < N_EDGES) {
        src = load_idx(ei, eid);
        dst = load_idx(ei, (long long)N_EDGES + eid);
    } else {
        src = dst = eid - N_EDGES;   // self loops appended
    }

    float4 l  = ((const float4*)(XL + (size_t)src * HID))[hl];
    float4 r  = ((const float4*)(XR + (size_t)dst * HID))[hl];
    float4 a4 = ((const float4*)att)[hl];

    float h0 = l.x + r.x, h1 = l.y + r.y, h2 = l.z + r.z, h3 = l.w + r.w;
    h0 = (h0 >= 0.0f) ? h0 : NEG_SLOPE * h0;
    h1 = (h1 >= 0.0f) ? h1 : NEG_SLOPE * h1;
    h2 = (h2 >= 0.0f) ? h2 : NEG_SLOPE * h2;
    h3 = (h3 >= 0.0f) ? h3 : NEG_SLOPE * h3;

    float e = a4.x * h0 + a4.y * h1 + a4.z * h2 + a4.w * h3;
#pragma unroll
    for (int o = 8; o; o >>= 1) e += __shfl_xor_sync(0xffffffffu, e, o);

    float a = __expf(e);

    if (hl == 0) atomicAdd(&Z[dst], a);
    float* aggp = AGG + (size_t)dst * HID + hl * 4;
    asm volatile("red.global.add.v4.f32 [%0], {%1, %2, %3, %4};"
                 :: "l"(aggp), "f"(a * l.x), "f"(a * l.y), "f"(a * l.z), "f"(a * l.w)
                 : "memory");
}

// ---------------- node finalize: h = act(agg / z + bias) ----------------
__global__ void finalize_kernel(const float* __restrict__ AGG, const float* __restrict__ Z,
                                const float* __restrict__ bias, float* __restrict__ OUT,
                                int do_relu) {
    int i = blockIdx.x * blockDim.x + threadIdx.x;
    if (i >= N_NODES * HID) return;
    int n = i >> 6;
    int c = i & 63;
    float v = AGG[i] / Z[n] + bias[c];
    if (do_relu) v = fmaxf(v, 0.0f);
    OUT[i] = v;
}

// ---------------- global mean pool (sums + counts) ----------------
__global__ void pool_kernel(const void* __restrict__ batch,
                            const float* __restrict__ H,
                            float* __restrict__ POOL, float* __restrict__ CNT) {
    int lane = threadIdx.x & 31;
    int half = lane >> 4;
    int hl   = lane & 15;
    int n    = (blockIdx.x * (blockDim.x >> 5) + (threadIdx.x >> 5)) * 2 + half;
    if (n >= N_NODES) return;
    int g = load_idx(batch, n);
    float4 v = ((const float4*)(H + (size_t)n * HID))[hl];
    float* pp = &POOL[g * HID + hl * 4];
    asm volatile("red.global.add.v4.f32 [%0], {%1, %2, %3, %4};"
                 :: "l"(pp), "f"(v.x), "f"(v.y), "f"(v.z), "f"(v.w)
                 : "memory");
    if (hl == 0) atomicAdd(&CNT[g], 1.0f);
}

// ---------------- head: fc1 ----------------
__global__ void fc1_kernel(const float* __restrict__ POOL, const float* __restrict__ CNT,
                           const float* __restrict__ W, const float* __restrict__ b,
                           float* __restrict__ Y) {
    int gi = blockIdx.x;          // 512
    int c  = threadIdx.x;         // 64
    __shared__ float gs[HID];
    float cnt = fmaxf(CNT[gi], 1.0f);
    gs[c] = POOL[gi * HID + c] / cnt;
    __syncthreads();
    float acc = b[c];
#pragma unroll 8
    for (int k = 0; k < HID; k++) acc = fmaf(gs[k], W[k * HID + c], acc);
    Y[gi * HID + c] = acc;
}

// ---------------- head: batchnorm stats ----------------
__global__ void bn_stats_kernel(const float* __restrict__ Y,
                                float* __restrict__ MU, float* __restrict__ RSIG) {
    int c = threadIdx.x;          // 64
    float s = 0.0f, s2 = 0.0f;
    for (int g = 0; g < N_GRAPHS; g++) {
        float v = Y[g * HID + c];
        s += v;
        s2 += v * v;
    }
    float mu  = s * (1.0f / N_GRAPHS);
    float var = s2 * (1.0f / N_GRAPHS) - mu * mu;
    MU[c]   = mu;
    RSIG[c] = rsqrtf(var + 1e-5f);
}

// ---------------- head: bn -> relu -> fc2 -> log_softmax ----------------
__global__ void head_kernel(const float* __restrict__ Y,
                            const float* __restrict__ MU, const float* __restrict__ RSIG,
                            const float* __restrict__ gamma, const float* __restrict__ beta,
                            const float* __restrict__ W2, const float* __restrict__ b2,
                            float* __restrict__ OUT) {
    int gi = blockIdx.x;          // 512
    int t  = threadIdx.x;         // 64
    __shared__ float ys[HID];
    __shared__ float os[OUT_CH];
    float v = Y[gi * HID + t];
    v = gamma[t] * (v - MU[t]) * RSIG[t] + beta[t];
    ys[t] = fmaxf(v, 0.0f);
    __syncthreads();
    if (t < OUT_CH) {
        float acc = b2[t];
#pragma unroll 8
        for (int k = 0; k < HID; k++) acc = fmaf(ys[k], W2[k * OUT_CH + t], acc);
        os[t] = acc;
    }
    __syncthreads();
    if (t == 0) {
        float m = -1e30f;
#pragma unroll
        for (int j = 0; j < OUT_CH; j++) m = fmaxf(m, os[j]);
        float s = 0.0f;
#pragma unroll
        for (int j = 0; j < OUT_CH; j++) s += expf(os[j] - m);
        float lse = m + logf(s);
        for (int j = 0; j < OUT_CH; j++) OUT[gi * OUT_CH + j] = os[j] - lse;
    }
}

// ---------------- launch ----------------
extern "C" void kernel_launch(void* const* d_in, const int* in_sizes, int n_in,
                              void* d_out, int out_size) {
    const float* x      = (const float*)d_in[0];
    const void*  ei     = d_in[1];
    const void*  batch  = d_in[2];
    const float* W_l1   = (const float*)d_in[3];
    const float* b_l1   = (const float*)d_in[4];
    const float* W_r1   = (const float*)d_in[5];
    const float* b_r1   = (const float*)d_in[6];
    const float* att1   = (const float*)d_in[7];
    const float* bias1  = (const float*)d_in[8];
    const float* W_l2   = (const float*)d_in[9];
    const float* b_l2   = (const float*)d_in[10];
    const float* W_r2   = (const float*)d_in[11];
    const float* b_r2   = (const float*)d_in[12];
    const float* att2   = (const float*)d_in[13];
    const float* bias2  = (const float*)d_in[14];
    const float* W_fc1  = (const float*)d_in[15];
    const float* b_fc1  = (const float*)d_in[16];
    const float* gamma  = (const float*)d_in[17];
    const float* beta   = (const float*)d_in[18];
    const float* W_fc2  = (const float*)d_in[19];
    const float* b_fc2  = (const float*)d_in[20];
    float*       out    = (float*)d_out;

    float *xl, *xr, *agg, *z, *h, *pool, *cnt, *y, *mu, *rsig;
    cudaGetSymbolAddress((void**)&xl,   g_xl);
    cudaGetSymbolAddress((void**)&xr,   g_xr);
    cudaGetSymbolAddress((void**)&agg,  g_agg);
    cudaGetSymbolAddress((void**)&z,    g_z);
    cudaGetSymbolAddress((void**)&h,    g_h);
    cudaGetSymbolAddress((void**)&pool, g_pool);
    cudaGetSymbolAddress((void**)&cnt,  g_cnt);
    cudaGetSymbolAddress((void**)&y,    g_y);
    cudaGetSymbolAddress((void**)&mu,   g_mu);
    cudaGetSymbolAddress((void**)&rsig, g_rsig);

    const int NH = N_NODES * HID;
    dim3 b256(256);

    detect_kernel<<<1, 1>>>((const int*)ei);

    // ---- layer 1 ----
    zero_kernel<<<(NH + N_NODES + 255) / 256, b256>>>(agg, NH + N_NODES); // agg then z? not contiguous
    zero_kernel<<<(N_NODES + 255) / 256, b256>>>(z, N_NODES);
    dual_linear_kernel<IN_CH><<<N_NODES / 32, b256>>>(x, W_l1, b_l1, W_r1, b_r1, xl, xr);
    edge_kernel<<<(E_TOT + 15) / 16, b256>>>(ei, att1, xl, xr, agg, z);
    finalize_kernel<<<(NH + 255) / 256, b256>>>(agg, z, bias1, h, 1);

    // ---- layer 2 ----
    zero_kernel<<<(NH + 255) / 256, b256>>>(agg, NH);
    zero_kernel<<<(N_NODES + 255) / 256, b256>>>(z, N_NODES);
    dual_linear_kernel<HID><<<N_NODES / 32, b256>>>(h, W_l2, b_l2, W_r2, b_r2, xl, xr);
    edge_kernel<<<(E_TOT + 15) / 16, b256>>>(ei, att2, xl, xr, agg, z);
    finalize_kernel<<<(NH + 255) / 256, b256>>>(agg, z, bias2, h, 0);

    // ---- pool + head ----
    zero_kernel<<<(N_GRAPHS * HID + 255) / 256, b256>>>(pool, N_GRAPHS * HID);
    zero_kernel<<<(N_GRAPHS + 255) / 256, b256>>>(cnt, N_GRAPHS);
    pool_kernel<<<(N_NODES + 15) / 16, b256>>>(batch, h, pool, cnt);
    fc1_kernel<<<N_GRAPHS, HID>>>(pool, cnt, W_fc1, b_fc1, y);
    bn_stats_kernel<<<1, HID>>>(y, mu, rsig);
    head_kernel<<<N_GRAPHS, HID>>>(y, mu, rsig, gamma, beta, W_fc2, b_fc2, out);
}

// round 5
// speedup vs baseline: 1.8828x; 1.1176x over previous
#include <cuda_runtime.h>
#include <cuda_fp16.h>
#include <math.h>

#define N_NODES   100000
#define N_EDGES   1600000
#define E_TOT     (N_EDGES + N_NODES)
#define IN_CH     128
#define HID       64
#define OUT_CH    16
#define N_GRAPHS  512
#define NEG_SLOPE 0.2f

// ---------------- scratch (device globals; no allocation allowed) ----------------
__device__ __half2 g_xl[(size_t)N_NODES * 32];   // HID/2 half2 per node
__device__ __half2 g_xr[(size_t)N_NODES * 32];
__device__ float   g_agg[(size_t)N_NODES * HID];
__device__ float   g_z[N_NODES];
__device__ float   g_h[(size_t)N_NODES * HID];
__device__ float   g_pool[N_GRAPHS * HID];
__device__ float   g_cnt[N_GRAPHS];
__device__ float   g_y[N_GRAPHS * HID];
__device__ float   g_mu[HID];
__device__ float   g_rsig[HID];
__device__ int     g_is64;   // 1 if indices are int64, 0 if int32

// ---------------- dtype detection ----------------
__global__ void detect_kernel(const int* __restrict__ w) {
    int ok64 = 1;
    for (int i = 0; i < 32; i++)
        if (w[2 * i + 1] != 0) ok64 = 0;
    g_is64 = ok64;
}

__device__ __forceinline__ int load_idx(const void* p, long long i) {
    if (g_is64) return (int)((const long long*)p)[i];
    return ((const int*)p)[i];
}

// ---------------- utility: zero fill (two regions in one launch) ----------------
__global__ void zero2_kernel(float* __restrict__ p1, int n1,
                             float* __restrict__ p2, int n2) {
    int i = blockIdx.x * blockDim.x + threadIdx.x;
    if (i < n1) p1[i] = 0.0f;
    if (i < n2) p2[i] = 0.0f;
}

// ---------------- dual linear: 32 nodes/block, 4 nodes x 2 channels/thread ----
// Outputs fp16 (half2 per channel pair). Each W float2 load feeds 8 FMAs.
template <int IN>
__global__ __launch_bounds__(256) void dual_linear_kernel(
        const float* __restrict__ X,
        const float* __restrict__ Wl, const float* __restrict__ bl,
        const float* __restrict__ Wr, const float* __restrict__ br,
        __half2* __restrict__ XL, __half2* __restrict__ XR) {
    int node0 = blockIdx.x * 32;
    int c2    = threadIdx.x & 31;    // half2 channel pair: channels 2*c2, 2*c2+1
    int sub   = threadIdx.x >> 5;    // 0..7, 4 nodes each
    __shared__ float xs[32][IN];

    for (int i = threadIdx.x; i < 32 * (IN / 4); i += 256) {
        int row = i / (IN / 4), col = i % (IN / 4);
        ((float4*)xs[row])[col] =
            ((const float4*)(X + (size_t)(node0 + row) * IN))[col];
    }
    __syncthreads();

    float accl[4][2], accr[4][2];
    float bl0 = bl[2 * c2], bl1 = bl[2 * c2 + 1];
    float br0 = br[2 * c2], br1 = br[2 * c2 + 1];
#pragma unroll
    for (int n = 0; n < 4; n++) {
        accl[n][0] = bl0; accl[n][1] = bl1;
        accr[n][0] = br0; accr[n][1] = br1;
    }

    const float (*xp)[IN] = (const float (*)[IN])xs[sub * 4];

    for (int k0 = 0; k0 < IN; k0 += 4) {
        float4 xv[4];
#pragma unroll
        for (int n = 0; n < 4; n++)
            xv[n] = *(const float4*)&xp[n][k0];
#pragma unroll
        for (int kk = 0; kk < 4; kk++) {
            float2 wl = *(const float2*)&Wl[(k0 + kk) * HID + 2 * c2];
            float2 wr = *(const float2*)&Wr[(k0 + kk) * HID + 2 * c2];
#pragma unroll
            for (int n = 0; n < 4; n++) {
                float xvv = (kk == 0) ? xv[n].x : (kk == 1) ? xv[n].y
                          : (kk == 2) ? xv[n].z : xv[n].w;
                accl[n][0] = fmaf(xvv, wl.x, accl[n][0]);
                accl[n][1] = fmaf(xvv, wl.y, accl[n][1]);
                accr[n][0] = fmaf(xvv, wr.x, accr[n][0]);
                accr[n][1] = fmaf(xvv, wr.y, accr[n][1]);
            }
        }
    }

#pragma unroll
    for (int n = 0; n < 4; n++) {
        size_t node = (size_t)(node0 + sub * 4 + n);
        XL[node * 32 + c2] = __floats2half2_rn(accl[n][0], accl[n][1]);
        XR[node * 32 + c2] = __floats2half2_rn(accr[n][0], accr[n][1]);
    }
}

// ---------------- edge pass: 16 lanes/edge, fp16 gather + fp32 red.v4 --------
// e = att . LeakyReLU(xl[src] + xr[dst]); a = exp(e)  (softmax max-subtraction
// cancels in the normalized result; |e| is O(1) here).
__global__ void edge_kernel(const void* __restrict__ ei,
                            const float* __restrict__ att,
                            const __half2* __restrict__ XL,
                            const __half2* __restrict__ XR,
                            float* __restrict__ AGG,
                            float* __restrict__ Z) {
    int lane = threadIdx.x & 31;
    int half = lane >> 4;            // which edge of the pair
    int hl   = lane & 15;            // lane within half-warp: channels 4*hl..4*hl+3
    int eid  = (blockIdx.x * (blockDim.x >> 5) + (threadIdx.x >> 5)) * 2 + half;
    if (eid >= E_TOT) return;

    int src, dst;
    if (eid < N_EDGES) {
        src = load_idx(ei, eid);
        dst = load_idx(ei, (long long)N_EDGES + eid);
    } else {
        src = dst = eid - N_EDGES;   // self loops appended
    }

    uint2 lraw = ((const uint2*)(XL + (size_t)src * 32))[hl];   // 4 halfs
    uint2 rraw = ((const uint2*)(XR + (size_t)dst * 32))[hl];
    float4 a4  = ((const float4*)att)[hl];

    float2 l01 = __half22float2(*(const __half2*)&lraw.x);
    float2 l23 = __half22float2(*(const __half2*)&lraw.y);
    float2 r01 = __half22float2(*(const __half2*)&rraw.x);
    float2 r23 = __half22float2(*(const __half2*)&rraw.y);

    float h0 = l01.x + r01.x, h1 = l01.y + r01.y;
    float h2 = l23.x + r23.x, h3 = l23.y + r23.y;
    h0 = (h0 >= 0.0f) ? h0 : NEG_SLOPE * h0;
    h1 = (h1 >= 0.0f) ? h1 : NEG_SLOPE * h1;
    h2 = (h2 >= 0.0f) ? h2 : NEG_SLOPE * h2;
    h3 = (h3 >= 0.0f) ? h3 : NEG_SLOPE * h3;

    float e = a4.x * h0 + a4.y * h1 + a4.z * h2 + a4.w * h3;
#pragma unroll
    for (int o = 8; o; o >>= 1) e += __shfl_xor_sync(0xffffffffu, e, o);

    float a = __expf(e);

    if (hl == 0) atomicAdd(&Z[dst], a);
    float* aggp = AGG + (size_t)dst * HID + hl * 4;
    asm volatile("red.global.add.v4.f32 [%0], {%1, %2, %3, %4};"
                 :: "l"(aggp), "f"(a * l01.x), "f"(a * l01.y),
                    "f"(a * l23.x), "f"(a * l23.y)
                 : "memory");
}

// ---------------- node finalize: h = act(agg / z + bias); optional agg re-zero
__global__ void finalize_kernel(float* __restrict__ AGG, const float* __restrict__ Z,
                                const float* __restrict__ bias, float* __restrict__ OUT,
                                int do_relu, int do_zero) {
    int i = blockIdx.x * blockDim.x + threadIdx.x;
    if (i >= N_NODES * HID) return;
    int n = i >> 6;
    int c = i & 63;
    float v = AGG[i] / Z[n] + bias[c];
    if (do_relu) v = fmaxf(v, 0.0f);
    OUT[i] = v;
    if (do_zero) AGG[i] = 0.0f;
}

// ---------------- global mean pool (sums + counts) ----------------
__global__ void pool_kernel(const void* __restrict__ batch,
                            const float* __restrict__ H,
                            float* __restrict__ POOL, float* __restrict__ CNT) {
    int lane = threadIdx.x & 31;
    int half = lane >> 4;
    int hl   = lane & 15;
    int n    = (blockIdx.x * (blockDim.x >> 5) + (threadIdx.x >> 5)) * 2 + half;
    if (n >= N_NODES) return;
    int g = load_idx(batch, n);
    float4 v = ((const float4*)(H + (size_t)n * HID))[hl];
    float* pp = &POOL[g * HID + hl * 4];
    asm volatile("red.global.add.v4.f32 [%0], {%1, %2, %3, %4};"
                 :: "l"(pp), "f"(v.x), "f"(v.y), "f"(v.z), "f"(v.w)
                 : "memory");
    if (hl == 0) atomicAdd(&CNT[g], 1.0f);
}

// ---------------- head: fc1 ----------------
__global__ void fc1_kernel(const float* __restrict__ POOL, const float* __restrict__ CNT,
                           const float* __restrict__ W, const float* __restrict__ b,
                           float* __restrict__ Y) {
    int gi = blockIdx.x;          // 512
    int c  = threadIdx.x;         // 64
    __shared__ float gs[HID];
    float cnt = fmaxf(CNT[gi], 1.0f);
    gs[c] = POOL[gi * HID + c] / cnt;
    __syncthreads();
    float acc = b[c];
#pragma unroll 8
    for (int k = 0; k < HID; k++) acc = fmaf(gs[k], W[k * HID + c], acc);
    Y[gi * HID + c] = acc;
}

// ---------------- head: batchnorm stats ----------------
__global__ void bn_stats_kernel(const float* __restrict__ Y,
                                float* __restrict__ MU, float* __restrict__ RSIG) {
    int c = threadIdx.x;          // 64
    float s = 0.0f, s2 = 0.0f;
    for (int g = 0; g < N_GRAPHS; g++) {
        float v = Y[g * HID + c];
        s += v;
        s2 += v * v;
    }
    float mu  = s * (1.0f / N_GRAPHS);
    float var = s2 * (1.0f / N_GRAPHS) - mu * mu;
    MU[c]   = mu;
    RSIG[c] = rsqrtf(var + 1e-5f);
}

// ---------------- head: bn -> relu -> fc2 -> log_softmax ----------------
__global__ void head_kernel(const float* __restrict__ Y,
                            const float* __restrict__ MU, const float* __restrict__ RSIG,
                            const float* __restrict__ gamma, const float* __restrict__ beta,
                            const float* __restrict__ W2, const float* __restrict__ b2,
                            float* __restrict__ OUT) {
    int gi = blockIdx.x;          // 512
    int t  = threadIdx.x;         // 64
    __shared__ float ys[HID];
    __shared__ float os[OUT_CH];
    float v = Y[gi * HID + t];
    v = gamma[t] * (v - MU[t]) * RSIG[t] + beta[t];
    ys[t] = fmaxf(v, 0.0f);
    __syncthreads();
    if (t < OUT_CH) {
        float acc = b2[t];
#pragma unroll 8
        for (int k = 0; k < HID; k++) acc = fmaf(ys[k], W2[k * OUT_CH + t], acc);
        os[t] = acc;
    }
    __syncthreads();
    if (t == 0) {
        float m = -1e30f;
#pragma unroll
        for (int j = 0; j < OUT_CH; j++) m = fmaxf(m, os[j]);
        float s = 0.0f;
#pragma unroll
        for (int j = 0; j < OUT_CH; j++) s += expf(os[j] - m);
        float lse = m + logf(s);
        for (int j = 0; j < OUT_CH; j++) OUT[gi * OUT_CH + j] = os[j] - lse;
    }
}

// ---------------- launch ----------------
extern "C" void kernel_launch(void* const* d_in, const int* in_sizes, int n_in,
                              void* d_out, int out_size) {
    const float* x      = (const float*)d_in[0];
    const void*  ei     = d_in[1];
    const void*  batch  = d_in[2];
    const float* W_l1   = (const float*)d_in[3];
    const float* b_l1   = (const float*)d_in[4];
    const float* W_r1   = (const float*)d_in[5];
    const float* b_r1   = (const float*)d_in[6];
    const float* att1   = (const float*)d_in[7];
    const float* bias1  = (const float*)d_in[8];
    const float* W_l2   = (const float*)d_in[9];
    const float* b_l2   = (const float*)d_in[10];
    const float* W_r2   = (const float*)d_in[11];
    const float* b_r2   = (const float*)d_in[12];
    const float* att2   = (const float*)d_in[13];
    const float* bias2  = (const float*)d_in[14];
    const float* W_fc1  = (const float*)d_in[15];
    const float* b_fc1  = (const float*)d_in[16];
    const float* gamma  = (const float*)d_in[17];
    const float* beta   = (const float*)d_in[18];
    const float* W_fc2  = (const float*)d_in[19];
    const float* b_fc2  = (const float*)d_in[20];
    float*       out    = (float*)d_out;

    __half2 *xl, *xr;
    float *agg, *z, *h, *pool, *cnt, *y, *mu, *rsig;
    cudaGetSymbolAddress((void**)&xl,   g_xl);
    cudaGetSymbolAddress((void**)&xr,   g_xr);
    cudaGetSymbolAddress((void**)&agg,  g_agg);
    cudaGetSymbolAddress((void**)&z,    g_z);
    cudaGetSymbolAddress((void**)&h,    g_h);
    cudaGetSymbolAddress((void**)&pool, g_pool);
    cudaGetSymbolAddress((void**)&cnt,  g_cnt);
    cudaGetSymbolAddress((void**)&y,    g_y);
    cudaGetSymbolAddress((void**)&mu,   g_mu);
    cudaGetSymbolAddress((void**)&rsig, g_rsig);

    const int NH = N_NODES * HID;
    dim3 b256(256);

    detect_kernel<<<1, 1>>>((const int*)ei);

    // ---- layer 1 ----
    zero2_kernel<<<(NH + 255) / 256, b256>>>(agg, NH, z, N_NODES);
    dual_linear_kernel<IN_CH><<<N_NODES / 32, b256>>>(x, W_l1, b_l1, W_r1, b_r1, xl, xr);
    edge_kernel<<<(E_TOT + 15) / 16, b256>>>(ei, att1, xl, xr, agg, z);
    finalize_kernel<<<(NH + 255) / 256, b256>>>(agg, z, bias1, h, 1, 1);  // re-zeros agg

    // ---- layer 2 ----
    zero2_kernel<<<(N_NODES + 255) / 256, b256>>>(z, N_NODES, z, N_NODES);
    dual_linear_kernel<HID><<<N_NODES / 32, b256>>>(h, W_l2, b_l2, W_r2, b_r2, xl, xr);
    edge_kernel<<<(E_TOT + 15) / 16, b256>>>(ei, att2, xl, xr, agg, z);
    finalize_kernel<<<(NH + 255) / 256, b256>>>(agg, z, bias2, h, 0, 0);

    // ---- pool + head ----
    zero2_kernel<<<(N_GRAPHS * HID + 255) / 256, b256>>>(pool, N_GRAPHS * HID, cnt, N_GRAPHS);
    pool_kernel<<<(N_NODES + 15) / 16, b256>>>(batch, h, pool, cnt);
    fc1_kernel<<<N_GRAPHS, HID>>>(pool, cnt, W_fc1, b_fc1, y);
    bn_stats_kernel<<<1, HID>>>(y, mu, rsig);
    head_kernel<<<N_GRAPHS, HID>>>(y, mu, rsig, gamma, beta, W_fc2, b_fc2, out);
}

// round 6
// speedup vs baseline: 2.3421x; 1.2439x over previous
#include <cuda_runtime.h>
#include <cuda_fp16.h>
#include <math.h>

#define N_NODES   100000
#define N_EDGES   1600000
#define E_TOT     (N_EDGES + N_NODES)
#define IN_CH     128
#define HID       64
#define OUT_CH    16
#define N_GRAPHS  512
#define NEG_SLOPE 0.2f

#define SCAN_BLK  512
#define N_SCAN_BLKS ((N_NODES + SCAN_BLK - 1) / SCAN_BLK)   // 196

// ---------------- scratch (device globals; no allocation allowed) ----------------
__device__ __half2 g_xl[(size_t)N_NODES * 32];
__device__ __half2 g_xr[(size_t)N_NODES * 32];
__device__ float   g_h[(size_t)N_NODES * HID];
__device__ float   g_pool[N_GRAPHS * HID];
__device__ float   g_cnt[N_GRAPHS];
__device__ float   g_y[N_GRAPHS * HID];
__device__ float   g_mu[HID];
__device__ float   g_rsig[HID];
__device__ int     g_is64;

// CSR scratch
__device__ int g_deg[N_NODES];
__device__ int g_rowptr[N_NODES + 1];
__device__ int g_cursor[N_NODES];
__device__ int g_col[E_TOT];
__device__ int g_bsum[N_SCAN_BLKS];

// ---------------- dtype detection ----------------
__global__ void detect_kernel(const int* __restrict__ w) {
    int ok64 = 1;
    for (int i = 0; i < 32; i++)
        if (w[2 * i + 1] != 0) ok64 = 0;
    g_is64 = ok64;
}

__device__ __forceinline__ int load_idx(const void* p, long long i) {
    if (g_is64) return (int)((const long long*)p)[i];
    return ((const int*)p)[i];
}

// ---------------- zero helpers ----------------
__global__ void zero_int_kernel(int* __restrict__ p, int n) {
    int i = blockIdx.x * blockDim.x + threadIdx.x;
    if (i < n) p[i] = 0;
}
__global__ void zero2_kernel(float* __restrict__ p1, int n1,
                             float* __restrict__ p2, int n2) {
    int i = blockIdx.x * blockDim.x + threadIdx.x;
    if (i < n1) p1[i] = 0.0f;
    if (i < n2) p2[i] = 0.0f;
}

// ---------------- CSR build ----------------
__global__ void hist_kernel(const void* __restrict__ ei, int* __restrict__ deg) {
    int e = blockIdx.x * blockDim.x + threadIdx.x;
    if (e >= E_TOT) return;
    int dst = (e < N_EDGES) ? load_idx(ei, (long long)N_EDGES + e) : e - N_EDGES;
    atomicAdd(&deg[dst], 1);
}

// phase 1: per-block exclusive scan of deg -> rowptr (block-local), block totals -> bsum
__global__ void scan1_kernel(const int* __restrict__ deg, int* __restrict__ rowptr,
                             int* __restrict__ bsum) {
    __shared__ int sh[SCAN_BLK];
    int i = blockIdx.x * SCAN_BLK + threadIdx.x;
    int v = (i < N_NODES) ? deg[i] : 0;
    sh[threadIdx.x] = v;
    __syncthreads();
    // Hillis-Steele inclusive scan
    for (int o = 1; o < SCAN_BLK; o <<= 1) {
        int t = (threadIdx.x >= o) ? sh[threadIdx.x - o] : 0;
        __syncthreads();
        sh[threadIdx.x] += t;
        __syncthreads();
    }
    if (i <= N_NODES && i < (blockIdx.x + 1) * SCAN_BLK + 1)
        if (i < N_NODES) rowptr[i] = sh[threadIdx.x] - v;   // exclusive within block
    if (threadIdx.x == SCAN_BLK - 1) bsum[blockIdx.x] = sh[SCAN_BLK - 1];
}

// phase 2: serial exclusive scan of block sums (196 elements)
__global__ void scan2_kernel(int* __restrict__ bsum) {
    if (threadIdx.x == 0) {
        int acc = 0;
        for (int b = 0; b < N_SCAN_BLKS; b++) {
            int t = bsum[b];
            bsum[b] = acc;
            acc += t;
        }
    }
}

// phase 3: add block offsets, init cursor, set rowptr[N]
__global__ void scan3_kernel(int* __restrict__ rowptr, const int* __restrict__ bsum,
                             int* __restrict__ cursor) {
    int i = blockIdx.x * SCAN_BLK + threadIdx.x;
    if (i < N_NODES) {
        int v = rowptr[i] + bsum[blockIdx.x];
        rowptr[i] = v;
        cursor[i] = v;
    }
    if (i == 0) rowptr[N_NODES] = E_TOT;
}

__global__ void scatter_kernel(const void* __restrict__ ei,
                               int* __restrict__ cursor, int* __restrict__ col) {
    int e = blockIdx.x * blockDim.x + threadIdx.x;
    if (e >= E_TOT) return;
    int src, dst;
    if (e < N_EDGES) {
        src = load_idx(ei, e);
        dst = load_idx(ei, (long long)N_EDGES + e);
    } else {
        src = dst = e - N_EDGES;
    }
    int pos = atomicAdd(&cursor[dst], 1);
    col[pos] = src;
}

// ---------------- dual linear: 32 nodes/block, 4 nodes x 2 channels/thread ----
template <int IN>
__global__ __launch_bounds__(256) void dual_linear_kernel(
        const float* __restrict__ X,
        const float* __restrict__ Wl, const float* __restrict__ bl,
        const float* __restrict__ Wr, const float* __restrict__ br,
        __half2* __restrict__ XL, __half2* __restrict__ XR) {
    int node0 = blockIdx.x * 32;
    int c2    = threadIdx.x & 31;
    int sub   = threadIdx.x >> 5;
    __shared__ float xs[32][IN];

    for (int i = threadIdx.x; i < 32 * (IN / 4); i += 256) {
        int row = i / (IN / 4), colx = i % (IN / 4);
        ((float4*)xs[row])[colx] =
            ((const float4*)(X + (size_t)(node0 + row) * IN))[colx];
    }
    __syncthreads();

    float accl[4][2], accr[4][2];
    float bl0 = bl[2 * c2], bl1 = bl[2 * c2 + 1];
    float br0 = br[2 * c2], br1 = br[2 * c2 + 1];
#pragma unroll
    for (int n = 0; n < 4; n++) {
        accl[n][0] = bl0; accl[n][1] = bl1;
        accr[n][0] = br0; accr[n][1] = br1;
    }

    const float (*xp)[IN] = (const float (*)[IN])xs[sub * 4];

    for (int k0 = 0; k0 < IN; k0 += 4) {
        float4 xv[4];
#pragma unroll
        for (int n = 0; n < 4; n++)
            xv[n] = *(const float4*)&xp[n][k0];
#pragma unroll
        for (int kk = 0; kk < 4; kk++) {
            float2 wl = *(const float2*)&Wl[(k0 + kk) * HID + 2 * c2];
            float2 wr = *(const float2*)&Wr[(k0 + kk) * HID + 2 * c2];
#pragma unroll
            for (int n = 0; n < 4; n++) {
                float xvv = (kk == 0) ? xv[n].x : (kk == 1) ? xv[n].y
                          : (kk == 2) ? xv[n].z : xv[n].w;
                accl[n][0] = fmaf(xvv, wl.x, accl[n][0]);
                accl[n][1] = fmaf(xvv, wl.y, accl[n][1]);
                accr[n][0] = fmaf(xvv, wr.x, accr[n][0]);
                accr[n][1] = fmaf(xvv, wr.y, accr[n][1]);
            }
        }
    }

#pragma unroll
    for (int n = 0; n < 4; n++) {
        size_t node = (size_t)(node0 + sub * 4 + n);
        XL[node * 32 + c2] = __floats2half2_rn(accl[n][0], accl[n][1]);
        XR[node * 32 + c2] = __floats2half2_rn(accr[n][0], accr[n][1]);
    }
}

// ---------------- GAT aggregate: warp per node, dst-centric, no atomics ------
// For each incoming edge: e = att . LeakyReLU(xl[src]+xr[node]); a = exp(e);
// acc += a*xl[src]; z += a.  Output h = act(acc/z + bias).  (Softmax max-shift
// cancels; |e| is O(1).)
__global__ __launch_bounds__(256) void gat_agg_kernel(
        const int* __restrict__ rowptr, const int* __restrict__ col,
        const __half2* __restrict__ XL, const __half2* __restrict__ XR,
        const float* __restrict__ att, const float* __restrict__ bias,
        float* __restrict__ OUT, int do_relu) {
    int node = blockIdx.x * 8 + (threadIdx.x >> 5);
    if (node >= N_NODES) return;
    int lane = threadIdx.x & 31;

    float2 r  = __half22float2(XR[(size_t)node * 32 + lane]);
    float2 a2 = ((const float2*)att)[lane];

    int beg = rowptr[node], end = rowptr[node + 1];
    float accx = 0.0f, accy = 0.0f, z = 0.0f;

    int e = beg;
    for (; e + 1 < end; e += 2) {
        int s0 = col[e], s1 = col[e + 1];
        float2 l0 = __half22float2(XL[(size_t)s0 * 32 + lane]);
        float2 l1 = __half22float2(XL[(size_t)s1 * 32 + lane]);

        float h0x = l0.x + r.x, h0y = l0.y + r.y;
        float h1x = l1.x + r.x, h1y = l1.y + r.y;
        h0x = (h0x >= 0.0f) ? h0x : NEG_SLOPE * h0x;
        h0y = (h0y >= 0.0f) ? h0y : NEG_SLOPE * h0y;
        h1x = (h1x >= 0.0f) ? h1x : NEG_SLOPE * h1x;
        h1y = (h1y >= 0.0f) ? h1y : NEG_SLOPE * h1y;

        float p0 = a2.x * h0x + a2.y * h0y;
        float p1 = a2.x * h1x + a2.y * h1y;
#pragma unroll
        for (int o = 16; o; o >>= 1) {
            p0 += __shfl_xor_sync(0xffffffffu, p0, o);
            p1 += __shfl_xor_sync(0xffffffffu, p1, o);
        }
        float w0 = __expf(p0);
        float w1 = __expf(p1);
        z += w0 + w1;
        accx = fmaf(w0, l0.x, accx); accx = fmaf(w1, l1.x, accx);
        accy = fmaf(w0, l0.y, accy); accy = fmaf(w1, l1.y, accy);
    }
    if (e < end) {
        int s0 = col[e];
        float2 l0 = __half22float2(XL[(size_t)s0 * 32 + lane]);
        float h0x = l0.x + r.x, h0y = l0.y + r.y;
        h0x = (h0x >= 0.0f) ? h0x : NEG_SLOPE * h0x;
        h0y = (h0y >= 0.0f) ? h0y : NEG_SLOPE * h0y;
        float p0 = a2.x * h0x + a2.y * h0y;
#pragma unroll
        for (int o = 16; o; o >>= 1)
            p0 += __shfl_xor_sync(0xffffffffu, p0, o);
        float w0 = __expf(p0);
        z += w0;
        accx = fmaf(w0, l0.x, accx);
        accy = fmaf(w0, l0.y, accy);
    }

    float inv = 1.0f / z;   // self-loop guarantees z > 0
    float2 bv = ((const float2*)bias)[lane];
    float ox = accx * inv + bv.x;
    float oy = accy * inv + bv.y;
    if (do_relu) { ox = fmaxf(ox, 0.0f); oy = fmaxf(oy, 0.0f); }
    ((float2*)(OUT + (size_t)node * HID))[lane] = make_float2(ox, oy);
}

// ---------------- global mean pool ----------------
__global__ void pool_kernel(const void* __restrict__ batch,
                            const float* __restrict__ H,
                            float* __restrict__ POOL, float* __restrict__ CNT) {
    int lane = threadIdx.x & 31;
    int half = lane >> 4;
    int hl   = lane & 15;
    int n    = (blockIdx.x * (blockDim.x >> 5) + (threadIdx.x >> 5)) * 2 + half;
    if (n >= N_NODES) return;
    int g = load_idx(batch, n);
    float4 v = ((const float4*)(H + (size_t)n * HID))[hl];
    float* pp = &POOL[g * HID + hl * 4];
    asm volatile("red.global.add.v4.f32 [%0], {%1, %2, %3, %4};"
                 :: "l"(pp), "f"(v.x), "f"(v.y), "f"(v.z), "f"(v.w)
                 : "memory");
    if (hl == 0) atomicAdd(&CNT[g], 1.0f);
}

// ---------------- head: fc1 ----------------
__global__ void fc1_kernel(const float* __restrict__ POOL, const float* __restrict__ CNT,
                           const float* __restrict__ W, const float* __restrict__ b,
                           float* __restrict__ Y) {
    int gi = blockIdx.x;
    int c  = threadIdx.x;
    __shared__ float gs[HID];
    float cnt = fmaxf(CNT[gi], 1.0f);
    gs[c] = POOL[gi * HID + c] / cnt;
    __syncthreads();
    float acc = b[c];
#pragma unroll 8
    for (int k = 0; k < HID; k++) acc = fmaf(gs[k], W[k * HID + c], acc);
    Y[gi * HID + c] = acc;
}

// ---------------- head: batchnorm stats ----------------
__global__ void bn_stats_kernel(const float* __restrict__ Y,
                                float* __restrict__ MU, float* __restrict__ RSIG) {
    int c = threadIdx.x;
    float s = 0.0f, s2 = 0.0f;
    for (int g = 0; g < N_GRAPHS; g++) {
        float v = Y[g * HID + c];
        s += v;
        s2 += v * v;
    }
    float mu  = s * (1.0f / N_GRAPHS);
    float var = s2 * (1.0f / N_GRAPHS) - mu * mu;
    MU[c]   = mu;
    RSIG[c] = rsqrtf(var + 1e-5f);
}

// ---------------- head: bn -> relu -> fc2 -> log_softmax ----------------
__global__ void head_kernel(const float* __restrict__ Y,
                            const float* __restrict__ MU, const float* __restrict__ RSIG,
                            const float* __restrict__ gamma, const float* __restrict__ beta,
                            const float* __restrict__ W2, const float* __restrict__ b2,
                            float* __restrict__ OUT) {
    int gi = blockIdx.x;
    int t  = threadIdx.x;
    __shared__ float ys[HID];
    __shared__ float os[OUT_CH];
    float v = Y[gi * HID + t];
    v = gamma[t] * (v - MU[t]) * RSIG[t] + beta[t];
    ys[t] = fmaxf(v, 0.0f);
    __syncthreads();
    if (t < OUT_CH) {
        float acc = b2[t];
#pragma unroll 8
        for (int k = 0; k < HID; k++) acc = fmaf(ys[k], W2[k * OUT_CH + t], acc);
        os[t] = acc;
    }
    __syncthreads();
    if (t == 0) {
        float m = -1e30f;
#pragma unroll
        for (int j = 0; j < OUT_CH; j++) m = fmaxf(m, os[j]);
        float s = 0.0f;
#pragma unroll
        for (int j = 0; j < OUT_CH; j++) s += expf(os[j] - m);
        float lse = m + logf(s);
        for (int j = 0; j < OUT_CH; j++) OUT[gi * OUT_CH + j] = os[j] - lse;
    }
}

// ---------------- launch ----------------
extern "C" void kernel_launch(void* const* d_in, const int* in_sizes, int n_in,
                              void* d_out, int out_size) {
    const float* x      = (const float*)d_in[0];
    const void*  ei     = d_in[1];
    const void*  batch  = d_in[2];
    const float* W_l1   = (const float*)d_in[3];
    const float* b_l1   = (const float*)d_in[4];
    const float* W_r1   = (const float*)d_in[5];
    const float* b_r1   = (const float*)d_in[6];
    const float* att1   = (const float*)d_in[7];
    const float* bias1  = (const float*)d_in[8];
    const float* W_l2   = (const float*)d_in[9];
    const float* b_l2   = (const float*)d_in[10];
    const float* W_r2   = (const float*)d_in[11];
    const float* b_r2   = (const float*)d_in[12];
    const float* att2   = (const float*)d_in[13];
    const float* bias2  = (const float*)d_in[14];
    const float* W_fc1  = (const float*)d_in[15];
    const float* b_fc1  = (const float*)d_in[16];
    const float* gamma  = (const float*)d_in[17];
    const float* beta   = (const float*)d_in[18];
    const float* W_fc2  = (const float*)d_in[19];
    const float* b_fc2  = (const float*)d_in[20];
    float*       out    = (float*)d_out;

    __half2 *xl, *xr;
    float *h, *pool, *cnt, *y, *mu, *rsig;
    int *deg, *rowptr, *cursor, *col, *bsum;
    cudaGetSymbolAddress((void**)&xl,     g_xl);
    cudaGetSymbolAddress((void**)&xr,     g_xr);
    cudaGetSymbolAddress((void**)&h,      g_h);
    cudaGetSymbolAddress((void**)&pool,   g_pool);
    cudaGetSymbolAddress((void**)&cnt,    g_cnt);
    cudaGetSymbolAddress((void**)&y,      g_y);
    cudaGetSymbolAddress((void**)&mu,     g_mu);
    cudaGetSymbolAddress((void**)&rsig,   g_rsig);
    cudaGetSymbolAddress((void**)&deg,    g_deg);
    cudaGetSymbolAddress((void**)&rowptr, g_rowptr);
    cudaGetSymbolAddress((void**)&cursor, g_cursor);
    cudaGetSymbolAddress((void**)&col,    g_col);
    cudaGetSymbolAddress((void**)&bsum,   g_bsum);

    dim3 b256(256);

    detect_kernel<<<1, 1>>>((const int*)ei);

    // ---- CSR build (shared by both layers) ----
    zero_int_kernel<<<(N_NODES + 255) / 256, b256>>>(deg, N_NODES);
    hist_kernel<<<(E_TOT + 255) / 256, b256>>>(ei, deg);
    scan1_kernel<<<N_SCAN_BLKS, SCAN_BLK>>>(deg, rowptr, bsum);
    scan2_kernel<<<1, 32>>>(bsum);
    scan3_kernel<<<N_SCAN_BLKS, SCAN_BLK>>>(rowptr, bsum, cursor);
    scatter_kernel<<<(E_TOT + 255) / 256, b256>>>(ei, cursor, col);

    // ---- layer 1 ----
    dual_linear_kernel<IN_CH><<<N_NODES / 32, b256>>>(x, W_l1, b_l1, W_r1, b_r1, xl, xr);
    gat_agg_kernel<<<(N_NODES + 7) / 8, b256>>>(rowptr, col, xl, xr, att1, bias1, h, 1);

    // ---- layer 2 ----
    dual_linear_kernel<HID><<<N_NODES / 32, b256>>>(h, W_l2, b_l2, W_r2, b_r2, xl, xr);
    gat_agg_kernel<<<(N_NODES + 7) / 8, b256>>>(rowptr, col, xl, xr, att2, bias2, h, 0);

    // ---- pool + head ----
    zero2_kernel<<<(N_GRAPHS * HID + 255) / 256, b256>>>(pool, N_GRAPHS * HID, cnt, N_GRAPHS);
    pool_kernel<<<(N_NODES + 15) / 16, b256>>>(batch, h, pool, cnt);
    fc1_kernel<<<N_GRAPHS, HID>>>(pool, cnt, W_fc1, b_fc1, y);
    bn_stats_kernel<<<1, HID>>>(y, mu, rsig);
    head_kernel<<<N_GRAPHS, HID>>>(y, mu, rsig, gamma, beta, W_fc2, b_fc2, out);
}

// round 7
// speedup vs baseline: 2.6119x; 1.1152x over previous
#include <cuda_runtime.h>
#include <cuda_fp16.h>
#include <math.h>

#define N_NODES   100000
#define N_EDGES   1600000
#define E_TOT     (N_EDGES + N_NODES)
#define IN_CH     128
#define HID       64
#define OUT_CH    16
#define N_GRAPHS  512
#define NEG_SLOPE 0.2f

#define SCAN_BLK  512
#define N_SCAN_BLKS ((N_NODES + SCAN_BLK - 1) / SCAN_BLK)   // 196

// ---------------- scratch (device globals; no allocation allowed) ----------------
__device__ __half2 g_xl[(size_t)N_NODES * 32];
__device__ __half2 g_xr[(size_t)N_NODES * 32];
__device__ float   g_h[(size_t)N_NODES * HID];
__device__ float   g_pool[N_GRAPHS * HID];
__device__ float   g_cnt[N_GRAPHS];
__device__ float   g_y[N_GRAPHS * HID];
__device__ float   g_mu[HID];
__device__ float   g_rsig[HID];
__device__ int     g_is64;

// CSR scratch
__device__ int g_deg[N_NODES];
__device__ int g_rowptr[N_NODES + 1];
__device__ int g_cursor[N_NODES];
__device__ int g_col[E_TOT];
__device__ int g_bsum[N_SCAN_BLKS];

// ---------------- packed f32x2 helpers ----------------
__device__ __forceinline__ unsigned long long pack2(float lo, float hi) {
    unsigned long long r;
    asm("mov.b64 %0, {%1, %2};" : "=l"(r) : "f"(lo), "f"(hi));
    return r;
}
__device__ __forceinline__ void unpack2(unsigned long long v, float& lo, float& hi) {
    asm("mov.b64 {%0, %1}, %2;" : "=f"(lo), "=f"(hi) : "l"(v));
}
__device__ __forceinline__ void fma2(unsigned long long& d,
                                     unsigned long long a, unsigned long long b) {
    asm("fma.rn.f32x2 %0, %1, %2, %0;" : "+l"(d) : "l"(a), "l"(b));
}

// ---------------- dtype detection ----------------
__global__ void detect_kernel(const int* __restrict__ w) {
    int ok64 = 1;
    for (int i = 0; i < 32; i++)
        if (w[2 * i + 1] != 0) ok64 = 0;
    g_is64 = ok64;
}

__device__ __forceinline__ int load_idx(const void* p, long long i) {
    if (g_is64) return (int)((const long long*)p)[i];
    return ((const int*)p)[i];
}

// ---------------- zero helpers ----------------
__global__ void zero_int_kernel(int* __restrict__ p, int n) {
    int i = blockIdx.x * blockDim.x + threadIdx.x;
    if (i < n) p[i] = 0;
}
__global__ void zero2_kernel(float* __restrict__ p1, int n1,
                             float* __restrict__ p2, int n2) {
    int i = blockIdx.x * blockDim.x + threadIdx.x;
    if (i < n1) p1[i] = 0.0f;
    if (i < n2) p2[i] = 0.0f;
}

// ---------------- CSR build ----------------
__global__ void hist_kernel(const void* __restrict__ ei, int* __restrict__ deg) {
    int e = blockIdx.x * blockDim.x + threadIdx.x;
    if (e >= E_TOT) return;
    int dst = (e < N_EDGES) ? load_idx(ei, (long long)N_EDGES + e) : e - N_EDGES;
    atomicAdd(&deg[dst], 1);
}

__global__ void scan1_kernel(const int* __restrict__ deg, int* __restrict__ rowptr,
                             int* __restrict__ bsum) {
    __shared__ int sh[SCAN_BLK];
    int i = blockIdx.x * SCAN_BLK + threadIdx.x;
    int v = (i < N_NODES) ? deg[i] : 0;
    sh[threadIdx.x] = v;
    __syncthreads();
    for (int o = 1; o < SCAN_BLK; o <<= 1) {
        int t = (threadIdx.x >= o) ? sh[threadIdx.x - o] : 0;
        __syncthreads();
        sh[threadIdx.x] += t;
        __syncthreads();
    }
    if (i < N_NODES) rowptr[i] = sh[threadIdx.x] - v;   // exclusive within block
    if (threadIdx.x == SCAN_BLK - 1) bsum[blockIdx.x] = sh[SCAN_BLK - 1];
}

__global__ void scan2_kernel(int* __restrict__ bsum) {
    if (threadIdx.x == 0) {
        int acc = 0;
        for (int b = 0; b < N_SCAN_BLKS; b++) {
            int t = bsum[b];
            bsum[b] = acc;
            acc += t;
        }
    }
}

__global__ void scan3_kernel(int* __restrict__ rowptr, const int* __restrict__ bsum,
                             int* __restrict__ cursor) {
    int i = blockIdx.x * SCAN_BLK + threadIdx.x;
    if (i < N_NODES) {
        int v = rowptr[i] + bsum[blockIdx.x];
        rowptr[i] = v;
        cursor[i] = v;
    }
    if (i == 0) rowptr[N_NODES] = E_TOT;
}

__global__ void scatter_kernel(const void* __restrict__ ei,
                               int* __restrict__ cursor, int* __restrict__ col) {
    int e = blockIdx.x * blockDim.x + threadIdx.x;
    if (e >= E_TOT) return;
    int src, dst;
    if (e < N_EDGES) {
        src = load_idx(ei, e);
        dst = load_idx(ei, (long long)N_EDGES + e);
    } else {
        src = dst = e - N_EDGES;
    }
    int pos = atomicAdd(&cursor[dst], 1);
    col[pos] = src;
}

// ---------------- dual linear (f32x2 packed FMA) -----------------------------
// 32 nodes/block; thread = (sub: 4 nodes) x (c2: channel pair).  Inner loop
// uses fma.rn.f32x2 -> SASS FFMA2, computing both channels per instruction.
template <int IN>
__global__ __launch_bounds__(256) void dual_linear_kernel(
        const float* __restrict__ X,
        const float* __restrict__ Wl, const float* __restrict__ bl,
        const float* __restrict__ Wr, const float* __restrict__ br,
        __half2* __restrict__ XL, __half2* __restrict__ XR) {
    int node0 = blockIdx.x * 32;
    int c2    = threadIdx.x & 31;
    int sub   = threadIdx.x >> 5;
    __shared__ float xs[32][IN];

    for (int i = threadIdx.x; i < 32 * (IN / 4); i += 256) {
        int row = i / (IN / 4), colx = i % (IN / 4);
        ((float4*)xs[row])[colx] =
            ((const float4*)(X + (size_t)(node0 + row) * IN))[colx];
    }
    __syncthreads();

    unsigned long long accl[4], accr[4];
    unsigned long long blv = *(const unsigned long long*)&bl[2 * c2];
    unsigned long long brv = *(const unsigned long long*)&br[2 * c2];
#pragma unroll
    for (int n = 0; n < 4; n++) { accl[n] = blv; accr[n] = brv; }

    const float (*xp)[IN] = (const float (*)[IN])xs[sub * 4];

    for (int k0 = 0; k0 < IN; k0 += 4) {
        float4 xv[4];
#pragma unroll
        for (int n = 0; n < 4; n++)
            xv[n] = *(const float4*)&xp[n][k0];
#pragma unroll
        for (int kk = 0; kk < 4; kk++) {
            unsigned long long wl2 =
                *(const unsigned long long*)&Wl[(k0 + kk) * HID + 2 * c2];
            unsigned long long wr2 =
                *(const unsigned long long*)&Wr[(k0 + kk) * HID + 2 * c2];
#pragma unroll
            for (int n = 0; n < 4; n++) {
                float xvv = (kk == 0) ? xv[n].x : (kk == 1) ? xv[n].y
                          : (kk == 2) ? xv[n].z : xv[n].w;
                unsigned long long xb = pack2(xvv, xvv);
                fma2(accl[n], xb, wl2);
                fma2(accr[n], xb, wr2);
            }
        }
    }

#pragma unroll
    for (int n = 0; n < 4; n++) {
        size_t node = (size_t)(node0 + sub * 4 + n);
        float l0, l1, r0, r1;
        unpack2(accl[n], l0, l1);
        unpack2(accr[n], r0, r1);
        XL[node * 32 + c2] = __floats2half2_rn(l0, l1);
        XR[node * 32 + c2] = __floats2half2_rn(r0, r1);
    }
}

// ---------------- GAT aggregate: warp per node, dst-centric, no f32 atomics --
// POOL_MODE=0: write h (with optional relu).  POOL_MODE=1: skip h, reduce the
// node result straight into pool[batch[node]] (+count).
template <int POOL_MODE>
__global__ __launch_bounds__(256) void gat_agg_kernel(
        const int* __restrict__ rowptr, const int* __restrict__ col,
        const __half2* __restrict__ XL, const __half2* __restrict__ XR,
        const float* __restrict__ att, const float* __restrict__ bias,
        float* __restrict__ OUT, int do_relu,
        const void* __restrict__ batch, float* __restrict__ POOL,
        float* __restrict__ CNT) {
    int node = blockIdx.x * 8 + (threadIdx.x >> 5);
    if (node >= N_NODES) return;
    int lane = threadIdx.x & 31;

    float2 r  = __half22float2(XR[(size_t)node * 32 + lane]);
    float2 a2 = ((const float2*)att)[lane];

    int beg = rowptr[node], end = rowptr[node + 1];
    float accx = 0.0f, accy = 0.0f, z = 0.0f;

    int e = beg;
    for (; e + 1 < end; e += 2) {
        int s0 = col[e], s1 = col[e + 1];
        float2 l0 = __half22float2(XL[(size_t)s0 * 32 + lane]);
        float2 l1 = __half22float2(XL[(size_t)s1 * 32 + lane]);

        float h0x = l0.x + r.x, h0y = l0.y + r.y;
        float h1x = l1.x + r.x, h1y = l1.y + r.y;
        h0x = (h0x >= 0.0f) ? h0x : NEG_SLOPE * h0x;
        h0y = (h0y >= 0.0f) ? h0y : NEG_SLOPE * h0y;
        h1x = (h1x >= 0.0f) ? h1x : NEG_SLOPE * h1x;
        h1y = (h1y >= 0.0f) ? h1y : NEG_SLOPE * h1y;

        float p0 = a2.x * h0x + a2.y * h0y;
        float p1 = a2.x * h1x + a2.y * h1y;
#pragma unroll
        for (int o = 16; o; o >>= 1) {
            p0 += __shfl_xor_sync(0xffffffffu, p0, o);
            p1 += __shfl_xor_sync(0xffffffffu, p1, o);
        }
        float w0 = __expf(p0);
        float w1 = __expf(p1);
        z += w0 + w1;
        accx = fmaf(w0, l0.x, accx); accx = fmaf(w1, l1.x, accx);
        accy = fmaf(w0, l0.y, accy); accy = fmaf(w1, l1.y, accy);
    }
    if (e < end) {
        int s0 = col[e];
        float2 l0 = __half22float2(XL[(size_t)s0 * 32 + lane]);
        float h0x = l0.x + r.x, h0y = l0.y + r.y;
        h0x = (h0x >= 0.0f) ? h0x : NEG_SLOPE * h0x;
        h0y = (h0y >= 0.0f) ? h0y : NEG_SLOPE * h0y;
        float p0 = a2.x * h0x + a2.y * h0y;
#pragma unroll
        for (int o = 16; o; o >>= 1)
            p0 += __shfl_xor_sync(0xffffffffu, p0, o);
        float w0 = __expf(p0);
        z += w0;
        accx = fmaf(w0, l0.x, accx);
        accy = fmaf(w0, l0.y, accy);
    }

    float inv = 1.0f / z;   // self-loop guarantees z > 0
    float2 bv = ((const float2*)bias)[lane];
    float ox = accx * inv + bv.x;
    float oy = accy * inv + bv.y;

    if (POOL_MODE == 0) {
        if (do_relu) { ox = fmaxf(ox, 0.0f); oy = fmaxf(oy, 0.0f); }
        ((float2*)(OUT + (size_t)node * HID))[lane] = make_float2(ox, oy);
    } else {
        int g = load_idx(batch, node);
        float* pp = &POOL[g * HID + 2 * lane];
        asm volatile("red.global.add.v2.f32 [%0], {%1, %2};"
                     :: "l"(pp), "f"(ox), "f"(oy) : "memory");
        if (lane == 0) atomicAdd(&CNT[g], 1.0f);
    }
}

// ---------------- head: fc1 ----------------
__global__ void fc1_kernel(const float* __restrict__ POOL, const float* __restrict__ CNT,
                           const float* __restrict__ W, const float* __restrict__ b,
                           float* __restrict__ Y) {
    int gi = blockIdx.x;
    int c  = threadIdx.x;
    __shared__ float gs[HID];
    float cnt = fmaxf(CNT[gi], 1.0f);
    gs[c] = POOL[gi * HID + c] / cnt;
    __syncthreads();
    float acc = b[c];
#pragma unroll 8
    for (int k = 0; k < HID; k++) acc = fmaf(gs[k], W[k * HID + c], acc);
    Y[gi * HID + c] = acc;
}

// ---------------- head: batchnorm stats ----------------
__global__ void bn_stats_kernel(const float* __restrict__ Y,
                                float* __restrict__ MU, float* __restrict__ RSIG) {
    int c = threadIdx.x;
    float s = 0.0f, s2 = 0.0f;
    for (int g = 0; g < N_GRAPHS; g++) {
        float v = Y[g * HID + c];
        s += v;
        s2 += v * v;
    }
    float mu  = s * (1.0f / N_GRAPHS);
    float var = s2 * (1.0f / N_GRAPHS) - mu * mu;
    MU[c]   = mu;
    RSIG[c] = rsqrtf(var + 1e-5f);
}

// ---------------- head: bn -> relu -> fc2 -> log_softmax ----------------
__global__ void head_kernel(const float* __restrict__ Y,
                            const float* __restrict__ MU, const float* __restrict__ RSIG,
                            const float* __restrict__ gamma, const float* __restrict__ beta,
                            const float* __restrict__ W2, const float* __restrict__ b2,
                            float* __restrict__ OUT) {
    int gi = blockIdx.x;
    int t  = threadIdx.x;
    __shared__ float ys[HID];
    __shared__ float os[OUT_CH];
    float v = Y[gi * HID + t];
    v = gamma[t] * (v - MU[t]) * RSIG[t] + beta[t];
    ys[t] = fmaxf(v, 0.0f);
    __syncthreads();
    if (t < OUT_CH) {
        float acc = b2[t];
#pragma unroll 8
        for (int k = 0; k < HID; k++) acc = fmaf(ys[k], W2[k * OUT_CH + t], acc);
        os[t] = acc;
    }
    __syncthreads();
    if (t == 0) {
        float m = -1e30f;
#pragma unroll
        for (int j = 0; j < OUT_CH; j++) m = fmaxf(m, os[j]);
        float s = 0.0f;
#pragma unroll
        for (int j = 0; j < OUT_CH; j++) s += expf(os[j] - m);
        float lse = m + logf(s);
        for (int j = 0; j < OUT_CH; j++) OUT[gi * OUT_CH + j] = os[j] - lse;
    }
}

// ---------------- launch ----------------
extern "C" void kernel_launch(void* const* d_in, const int* in_sizes, int n_in,
                              void* d_out, int out_size) {
    const float* x      = (const float*)d_in[0];
    const void*  ei     = d_in[1];
    const void*  batch  = d_in[2];
    const float* W_l1   = (const float*)d_in[3];
    const float* b_l1   = (const float*)d_in[4];
    const float* W_r1   = (const float*)d_in[5];
    const float* b_r1   = (const float*)d_in[6];
    const float* att1   = (const float*)d_in[7];
    const float* bias1  = (const float*)d_in[8];
    const float* W_l2   = (const float*)d_in[9];
    const float* b_l2   = (const float*)d_in[10];
    const float* W_r2   = (const float*)d_in[11];
    const float* b_r2   = (const float*)d_in[12];
    const float* att2   = (const float*)d_in[13];
    const float* bias2  = (const float*)d_in[14];
    const float* W_fc1  = (const float*)d_in[15];
    const float* b_fc1  = (const float*)d_in[16];
    const float* gamma  = (const float*)d_in[17];
    const float* beta   = (const float*)d_in[18];
    const float* W_fc2  = (const float*)d_in[19];
    const float* b_fc2  = (const float*)d_in[20];
    float*       out    = (float*)d_out;

    __half2 *xl, *xr;
    float *h, *pool, *cnt, *y, *mu, *rsig;
    int *deg, *rowptr, *cursor, *col, *bsum;
    cudaGetSymbolAddress((void**)&xl,     g_xl);
    cudaGetSymbolAddress((void**)&xr,     g_xr);
    cudaGetSymbolAddress((void**)&h,      g_h);
    cudaGetSymbolAddress((void**)&pool,   g_pool);
    cudaGetSymbolAddress((void**)&cnt,    g_cnt);
    cudaGetSymbolAddress((void**)&y,      g_y);
    cudaGetSymbolAddress((void**)&mu,     g_mu);
    cudaGetSymbolAddress((void**)&rsig,   g_rsig);
    cudaGetSymbolAddress((void**)&deg,    g_deg);
    cudaGetSymbolAddress((void**)&rowptr, g_rowptr);
    cudaGetSymbolAddress((void**)&cursor, g_cursor);
    cudaGetSymbolAddress((void**)&col,    g_col);
    cudaGetSymbolAddress((void**)&bsum,   g_bsum);

    dim3 b256(256);

    detect_kernel<<<1, 1>>>((const int*)ei);

    // ---- CSR build (shared by both layers); pool/cnt zeroed here too ----
    zero_int_kernel<<<(N_NODES + 255) / 256, b256>>>(deg, N_NODES);
    zero2_kernel<<<(N_GRAPHS * HID + 255) / 256, b256>>>(pool, N_GRAPHS * HID, cnt, N_GRAPHS);
    hist_kernel<<<(E_TOT + 255) / 256, b256>>>(ei, deg);
    scan1_kernel<<<N_SCAN_BLKS, SCAN_BLK>>>(deg, rowptr, bsum);
    scan2_kernel<<<1, 32>>>(bsum);
    scan3_kernel<<<N_SCAN_BLKS, SCAN_BLK>>>(rowptr, bsum, cursor);
    scatter_kernel<<<(E_TOT + 255) / 256, b256>>>(ei, cursor, col);

    // ---- layer 1 ----
    dual_linear_kernel<IN_CH><<<N_NODES / 32, b256>>>(x, W_l1, b_l1, W_r1, b_r1, xl, xr);
    gat_agg_kernel<0><<<(N_NODES + 7) / 8, b256>>>(rowptr, col, xl, xr, att1, bias1,
                                                   h, 1, batch, pool, cnt);

    // ---- layer 2 (pool fused into aggregation) ----
    dual_linear_kernel<HID><<<N_NODES / 32, b256>>>(h, W_l2, b_l2, W_r2, b_r2, xl, xr);
    gat_agg_kernel<1><<<(N_NODES + 7) / 8, b256>>>(rowptr, col, xl, xr, att2, bias2,
                                                   h, 0, batch, pool, cnt);

    // ---- head ----
    fc1_kernel<<<N_GRAPHS, HID>>>(pool, cnt, W_fc1, b_fc1, y);
    bn_stats_kernel<<<1, HID>>>(y, mu, rsig);
    head_kernel<<<N_GRAPHS, HID>>>(y, mu, rsig, gamma, beta, W_fc2, b_fc2, out);
}

// round 8
// speedup vs baseline: 2.6269x; 1.0057x over previous
#include <cuda_runtime.h>
#include <cuda_fp16.h>
#include <math.h>

#define N_NODES   100000
#define N_EDGES   1600000
#define E_TOT     (N_EDGES + N_NODES)
#define IN_CH     128
#define HID       64
#define OUT_CH    16
#define N_GRAPHS  512
#define NEG_SLOPE 0.2f

#define SCAN_BLK  512
#define N_SCAN_BLKS ((N_NODES + SCAN_BLK - 1) / SCAN_BLK)   // 196

// ---------------- scratch (device globals; no allocation allowed) ----------------
__device__ __half2 g_xl[(size_t)N_NODES * 32];
__device__ __half2 g_xr[(size_t)N_NODES * 32];
__device__ float   g_h[(size_t)N_NODES * HID];
__device__ float   g_pool[N_GRAPHS * HID];
__device__ float   g_cnt[N_GRAPHS];
__device__ float   g_y[N_GRAPHS * HID];
__device__ float   g_mu[HID];
__device__ float   g_rsig[HID];
__device__ int     g_is64;

// CSR scratch
__device__ int g_deg[N_NODES];
__device__ int g_rowptr[N_NODES + 1];
__device__ int g_cursor[N_NODES];
__device__ int g_col[E_TOT];
__device__ int g_bsum[N_SCAN_BLKS];

// ---------------- packed f32x2 helpers ----------------
__device__ __forceinline__ unsigned long long pack2(float lo, float hi) {
    unsigned long long r;
    asm("mov.b64 %0, {%1, %2};" : "=l"(r) : "f"(lo), "f"(hi));
    return r;
}
__device__ __forceinline__ void unpack2(unsigned long long v, float& lo, float& hi) {
    asm("mov.b64 {%0, %1}, %2;" : "=f"(lo), "=f"(hi) : "l"(v));
}
__device__ __forceinline__ void fma2(unsigned long long& d,
                                     unsigned long long a, unsigned long long b) {
    asm("fma.rn.f32x2 %0, %1, %2, %0;" : "+l"(d) : "l"(a), "l"(b));
}

// ---------------- dtype detection ----------------
__global__ void detect_kernel(const int* __restrict__ w) {
    int ok64 = 1;
    for (int i = 0; i < 32; i++)
        if (w[2 * i + 1] != 0) ok64 = 0;
    g_is64 = ok64;
}

__device__ __forceinline__ int load_idx(const void* p, long long i) {
    if (g_is64) return (int)((const long long*)p)[i];
    return ((const int*)p)[i];
}

// ---------------- zero helpers ----------------
__global__ void zero_int_kernel(int* __restrict__ p, int n) {
    int i = blockIdx.x * blockDim.x + threadIdx.x;
    if (i < n) p[i] = 0;
}
__global__ void zero2_kernel(float* __restrict__ p1, int n1,
                             float* __restrict__ p2, int n2) {
    int i = blockIdx.x * blockDim.x + threadIdx.x;
    if (i < n1) p1[i] = 0.0f;
    if (i < n2) p2[i] = 0.0f;
}

// ---------------- CSR build (2 edges/thread) ----------------
__global__ void hist_kernel(const void* __restrict__ ei, int* __restrict__ deg) {
    int t = blockIdx.x * blockDim.x + threadIdx.x;
#pragma unroll
    for (int u = 0; u < 2; u++) {
        int e = t * 2 + u;
        if (e >= E_TOT) return;
        int dst = (e < N_EDGES) ? load_idx(ei, (long long)N_EDGES + e) : e - N_EDGES;
        atomicAdd(&deg[dst], 1);
    }
}

__global__ void scan1_kernel(const int* __restrict__ deg, int* __restrict__ rowptr,
                             int* __restrict__ bsum) {
    __shared__ int sh[SCAN_BLK];
    int i = blockIdx.x * SCAN_BLK + threadIdx.x;
    int v = (i < N_NODES) ? deg[i] : 0;
    sh[threadIdx.x] = v;
    __syncthreads();
    for (int o = 1; o < SCAN_BLK; o <<= 1) {
        int t = (threadIdx.x >= o) ? sh[threadIdx.x - o] : 0;
        __syncthreads();
        sh[threadIdx.x] += t;
        __syncthreads();
    }
    if (i < N_NODES) rowptr[i] = sh[threadIdx.x] - v;
    if (threadIdx.x == SCAN_BLK - 1) bsum[blockIdx.x] = sh[SCAN_BLK - 1];
}

__global__ void scan2_kernel(int* __restrict__ bsum) {
    if (threadIdx.x == 0) {
        int acc = 0;
        for (int b = 0; b < N_SCAN_BLKS; b++) {
            int t = bsum[b];
            bsum[b] = acc;
            acc += t;
        }
    }
}

__global__ void scan3_kernel(int* __restrict__ rowptr, const int* __restrict__ bsum,
                             int* __restrict__ cursor) {
    int i = blockIdx.x * SCAN_BLK + threadIdx.x;
    if (i < N_NODES) {
        int v = rowptr[i] + bsum[blockIdx.x];
        rowptr[i] = v;
        cursor[i] = v;
    }
    if (i == 0) rowptr[N_NODES] = E_TOT;
}

__global__ void scatter_kernel(const void* __restrict__ ei,
                               int* __restrict__ cursor, int* __restrict__ col) {
    int t = blockIdx.x * blockDim.x + threadIdx.x;
#pragma unroll
    for (int u = 0; u < 2; u++) {
        int e = t * 2 + u;
        if (e >= E_TOT) return;
        int src, dst;
        if (e < N_EDGES) {
            src = load_idx(ei, e);
            dst = load_idx(ei, (long long)N_EDGES + e);
        } else {
            src = dst = e - N_EDGES;
        }
        int pos = atomicAdd(&cursor[dst], 1);
        col[pos] = src;
    }
}

// ---------------- dual linear (f32x2 packed FMA) -----------------------------
template <int IN>
__global__ __launch_bounds__(256) void dual_linear_kernel(
        const float* __restrict__ X,
        const float* __restrict__ Wl, const float* __restrict__ bl,
        const float* __restrict__ Wr, const float* __restrict__ br,
        __half2* __restrict__ XL, __half2* __restrict__ XR) {
    int node0 = blockIdx.x * 32;
    int c2    = threadIdx.x & 31;
    int sub   = threadIdx.x >> 5;
    __shared__ float xs[32][IN];

    for (int i = threadIdx.x; i < 32 * (IN / 4); i += 256) {
        int row = i / (IN / 4), colx = i % (IN / 4);
        ((float4*)xs[row])[colx] =
            ((const float4*)(X + (size_t)(node0 + row) * IN))[colx];
    }
    __syncthreads();

    unsigned long long accl[4], accr[4];
    unsigned long long blv = *(const unsigned long long*)&bl[2 * c2];
    unsigned long long brv = *(const unsigned long long*)&br[2 * c2];
#pragma unroll
    for (int n = 0; n < 4; n++) { accl[n] = blv; accr[n] = brv; }

    const float (*xp)[IN] = (const float (*)[IN])xs[sub * 4];

    for (int k0 = 0; k0 < IN; k0 += 4) {
        float4 xv[4];
#pragma unroll
        for (int n = 0; n < 4; n++)
            xv[n] = *(const float4*)&xp[n][k0];
#pragma unroll
        for (int kk = 0; kk < 4; kk++) {
            unsigned long long wl2 =
                *(const unsigned long long*)&Wl[(k0 + kk) * HID + 2 * c2];
            unsigned long long wr2 =
                *(const unsigned long long*)&Wr[(k0 + kk) * HID + 2 * c2];
#pragma unroll
            for (int n = 0; n < 4; n++) {
                float xvv = (kk == 0) ? xv[n].x : (kk == 1) ? xv[n].y
                          : (kk == 2) ? xv[n].z : xv[n].w;
                unsigned long long xb = pack2(xvv, xvv);
                fma2(accl[n], xb, wl2);
                fma2(accr[n], xb, wr2);
            }
        }
    }

#pragma unroll
    for (int n = 0; n < 4; n++) {
        size_t node = (size_t)(node0 + sub * 4 + n);
        float l0, l1, r0, r1;
        unpack2(accl[n], l0, l1);
        unpack2(accr[n], r0, r1);
        XL[node * 32 + c2] = __floats2half2_rn(l0, l1);
        XR[node * 32 + c2] = __floats2half2_rn(r0, r1);
    }
}

// ---------------- GAT aggregate: warp/node, 4-edge unroll, no f32 atomics ----
template <int POOL_MODE>
__global__ __launch_bounds__(256) void gat_agg_kernel(
        const int* __restrict__ rowptr, const int* __restrict__ col,
        const __half2* __restrict__ XL, const __half2* __restrict__ XR,
        const float* __restrict__ att, const float* __restrict__ bias,
        float* __restrict__ OUT, int do_relu,
        const void* __restrict__ batch, float* __restrict__ POOL,
        float* __restrict__ CNT) {
    int node = blockIdx.x * 8 + (threadIdx.x >> 5);
    if (node >= N_NODES) return;
    int lane = threadIdx.x & 31;

    float2 r  = __half22float2(XR[(size_t)node * 32 + lane]);
    float2 a2 = ((const float2*)att)[lane];

    int beg = rowptr[node], end = rowptr[node + 1];
    float accx = 0.0f, accy = 0.0f, z = 0.0f;

    int e = beg;
    // 4-edge unrolled main loop: 4 independent gathers + 4 shuffle chains
    for (; e + 3 < end; e += 4) {
        float2 l[4];
        float p[4];
#pragma unroll
        for (int u = 0; u < 4; u++) {
            int s = col[e + u];
            l[u] = __half22float2(XL[(size_t)s * 32 + lane]);
            float hx = l[u].x + r.x, hy = l[u].y + r.y;
            hx = (hx >= 0.0f) ? hx : NEG_SLOPE * hx;
            hy = (hy >= 0.0f) ? hy : NEG_SLOPE * hy;
            p[u] = a2.x * hx + a2.y * hy;
        }
#pragma unroll
        for (int o = 16; o; o >>= 1) {
#pragma unroll
            for (int u = 0; u < 4; u++)
                p[u] += __shfl_xor_sync(0xffffffffu, p[u], o);
        }
#pragma unroll
        for (int u = 0; u < 4; u++) {
            float w = __expf(p[u]);
            z += w;
            accx = fmaf(w, l[u].x, accx);
            accy = fmaf(w, l[u].y, accy);
        }
    }
    // remainder
    for (; e < end; e++) {
        int s = col[e];
        float2 l0 = __half22float2(XL[(size_t)s * 32 + lane]);
        float hx = l0.x + r.x, hy = l0.y + r.y;
        hx = (hx >= 0.0f) ? hx : NEG_SLOPE * hx;
        hy = (hy >= 0.0f) ? hy : NEG_SLOPE * hy;
        float p0 = a2.x * hx + a2.y * hy;
#pragma unroll
        for (int o = 16; o; o >>= 1)
            p0 += __shfl_xor_sync(0xffffffffu, p0, o);
        float w = __expf(p0);
        z += w;
        accx = fmaf(w, l0.x, accx);
        accy = fmaf(w, l0.y, accy);
    }

    float inv = 1.0f / z;   // self-loop guarantees z > 0
    float2 bv = ((const float2*)bias)[lane];
    float ox = accx * inv + bv.x;
    float oy = accy * inv + bv.y;

    if (POOL_MODE == 0) {
        if (do_relu) { ox = fmaxf(ox, 0.0f); oy = fmaxf(oy, 0.0f); }
        ((float2*)(OUT + (size_t)node * HID))[lane] = make_float2(ox, oy);
    } else {
        int g = load_idx(batch, node);
        float* pp = &POOL[g * HID + 2 * lane];
        asm volatile("red.global.add.v2.f32 [%0], {%1, %2};"
                     :: "l"(pp), "f"(ox), "f"(oy) : "memory");
        if (lane == 0) atomicAdd(&CNT[g], 1.0f);
    }
}

// ---------------- head: fc1 ----------------
__global__ void fc1_kernel(const float* __restrict__ POOL, const float* __restrict__ CNT,
                           const float* __restrict__ W, const float* __restrict__ b,
                           float* __restrict__ Y) {
    int gi = blockIdx.x;
    int c  = threadIdx.x;
    __shared__ float gs[HID];
    float cnt = fmaxf(CNT[gi], 1.0f);
    gs[c] = POOL[gi * HID + c] / cnt;
    __syncthreads();
    float acc = b[c];
#pragma unroll 8
    for (int k = 0; k < HID; k++) acc = fmaf(gs[k], W[k * HID + c], acc);
    Y[gi * HID + c] = acc;
}

// ---------------- head: batchnorm stats (parallel over 4 graph chunks) -------
__global__ void bn_stats_kernel(const float* __restrict__ Y,
                                float* __restrict__ MU, float* __restrict__ RSIG) {
    __shared__ float ss[4][HID], ss2[4][HID];
    int c     = threadIdx.x & 63;
    int chunk = threadIdx.x >> 6;   // 0..3, 128 graphs each
    float s = 0.0f, s2 = 0.0f;
    for (int g = chunk * 128; g < (chunk + 1) * 128; g++) {
        float v = Y[g * HID + c];
        s += v;
        s2 += v * v;
    }
    ss[chunk][c] = s;
    ss2[chunk][c] = s2;
    __syncthreads();
    if (chunk == 0) {
        s  = ss[0][c] + ss[1][c] + ss[2][c] + ss[3][c];
        s2 = ss2[0][c] + ss2[1][c] + ss2[2][c] + ss2[3][c];
        float mu  = s * (1.0f / N_GRAPHS);
        float var = s2 * (1.0f / N_GRAPHS) - mu * mu;
        MU[c]   = mu;
        RSIG[c] = rsqrtf(var + 1e-5f);
    }
}

// ---------------- head: bn -> relu -> fc2 -> log_softmax ----------------
__global__ void head_kernel(const float* __restrict__ Y,
                            const float* __restrict__ MU, const float* __restrict__ RSIG,
                            const float* __restrict__ gamma, const float* __restrict__ beta,
                            const float* __restrict__ W2, const float* __restrict__ b2,
                            float* __restrict__ OUT) {
    int gi = blockIdx.x;
    int t  = threadIdx.x;
    __shared__ float ys[HID];
    __shared__ float os[OUT_CH];
    float v = Y[gi * HID + t];
    v = gamma[t] * (v - MU[t]) * RSIG[t] + beta[t];
    ys[t] = fmaxf(v, 0.0f);
    __syncthreads();
    if (t < OUT_CH) {
        float acc = b2[t];
#pragma unroll 8
        for (int k = 0; k < HID; k++) acc = fmaf(ys[k], W2[k * OUT_CH + t], acc);
        os[t] = acc;
    }
    __syncthreads();
    if (t == 0) {
        float m = -1e30f;
#pragma unroll
        for (int j = 0; j < OUT_CH; j++) m = fmaxf(m, os[j]);
        float s = 0.0f;
#pragma unroll
        for (int j = 0; j < OUT_CH; j++) s += expf(os[j] - m);
        float lse = m + logf(s);
        for (int j = 0; j < OUT_CH; j++) OUT[gi * OUT_CH + j] = os[j] - lse;
    }
}

// ---------------- launch ----------------
extern "C" void kernel_launch(void* const* d_in, const int* in_sizes, int n_in,
                              void* d_out, int out_size) {
    const float* x      = (const float*)d_in[0];
    const void*  ei     = d_in[1];
    const void*  batch  = d_in[2];
    const float* W_l1   = (const float*)d_in[3];
    const float* b_l1   = (const float*)d_in[4];
    const float* W_r1   = (const float*)d_in[5];
    const float* b_r1   = (const float*)d_in[6];
    const float* att1   = (const float*)d_in[7];
    const float* bias1  = (const float*)d_in[8];
    const float* W_l2   = (const float*)d_in[9];
    const float* b_l2   = (const float*)d_in[10];
    const float* W_r2   = (const float*)d_in[11];
    const float* b_r2   = (const float*)d_in[12];
    const float* att2   = (const float*)d_in[13];
    const float* bias2  = (const float*)d_in[14];
    const float* W_fc1  = (const float*)d_in[15];
    const float* b_fc1  = (const float*)d_in[16];
    const float* gamma  = (const float*)d_in[17];
    const float* beta   = (const float*)d_in[18];
    const float* W_fc2  = (const float*)d_in[19];
    const float* b_fc2  = (const float*)d_in[20];
    float*       out    = (float*)d_out;

    __half2 *xl, *xr;
    float *h, *pool, *cnt, *y, *mu, *rsig;
    int *deg, *rowptr, *cursor, *col, *bsum;
    cudaGetSymbolAddress((void**)&xl,     g_xl);
    cudaGetSymbolAddress((void**)&xr,     g_xr);
    cudaGetSymbolAddress((void**)&h,      g_h);
    cudaGetSymbolAddress((void**)&pool,   g_pool);
    cudaGetSymbolAddress((void**)&cnt,    g_cnt);
    cudaGetSymbolAddress((void**)&y,      g_y);
    cudaGetSymbolAddress((void**)&mu,     g_mu);
    cudaGetSymbolAddress((void**)&rsig,   g_rsig);
    cudaGetSymbolAddress((void**)&deg,    g_deg);
    cudaGetSymbolAddress((void**)&rowptr, g_rowptr);
    cudaGetSymbolAddress((void**)&cursor, g_cursor);
    cudaGetSymbolAddress((void**)&col,    g_col);
    cudaGetSymbolAddress((void**)&bsum,   g_bsum);

    dim3 b256(256);

    detect_kernel<<<1, 1>>>((const int*)ei);

    // ---- CSR build (shared by both layers); pool/cnt zeroed here too ----
    zero_int_kernel<<<(N_NODES + 255) / 256, b256>>>(deg, N_NODES);
    zero2_kernel<<<(N_GRAPHS * HID + 255) / 256, b256>>>(pool, N_GRAPHS * HID, cnt, N_GRAPHS);
    hist_kernel<<<(E_TOT / 2 + 255) / 256, b256>>>(ei, deg);
    scan1_kernel<<<N_SCAN_BLKS, SCAN_BLK>>>(deg, rowptr, bsum);
    scan2_kernel<<<1, 32>>>(bsum);
    scan3_kernel<<<N_SCAN_BLKS, SCAN_BLK>>>(rowptr, bsum, cursor);
    scatter_kernel<<<(E_TOT / 2 + 255) / 256, b256>>>(ei, cursor, col);

    // ---- layer 1 ----
    dual_linear_kernel<IN_CH><<<N_NODES / 32, b256>>>(x, W_l1, b_l1, W_r1, b_r1, xl, xr);
    gat_agg_kernel<0><<<(N_NODES + 7) / 8, b256>>>(rowptr, col, xl, xr, att1, bias1,
                                                   h, 1, batch, pool, cnt);

    // ---- layer 2 (pool fused into aggregation) ----
    dual_linear_kernel<HID><<<N_NODES / 32, b256>>>(h, W_l2, b_l2, W_r2, b_r2, xl, xr);
    gat_agg_kernel<1><<<(N_NODES + 7) / 8, b256>>>(rowptr, col, xl, xr, att2, bias2,
                                                   h, 0, batch, pool, cnt);

    // ---- head ----
    fc1_kernel<<<N_GRAPHS, HID>>>(pool, cnt, W_fc1, b_fc1, y);
    bn_stats_kernel<<<1, 256>>>(y, mu, rsig);
    head_kernel<<<N_GRAPHS, HID>>>(y, mu, rsig, gamma, beta, W_fc2, b_fc2, out);
}